// round 4
// baseline (speedup 1.0000x reference)
#include <cuda_runtime.h>

#define BS   1024
#define DM   512
#define NH   8
#define DK   64
#define HIST 199
#define TT   200
#define TTILE 4
#define NTILES 50

// Scratch (static device allocation is allowed)
__device__ float g_q[BS * DM];        // 2 MB
__device__ float g_r[BS * NH * DM];   // 16 MB
__device__ float g_c[BS * NH * DM];   // 16 MB

typedef unsigned long long u64;

// ---- packed f32x2 helpers --------------------------------------------------
__device__ __forceinline__ u64 pack2(float x, float y) {
    u64 r; asm("mov.b64 %0, {%1, %2};" : "=l"(r) : "f"(x), "f"(y)); return r;
}
__device__ __forceinline__ float2 unpack2(u64 v) {
    float2 d; asm("mov.b64 {%0, %1}, %2;" : "=f"(d.x), "=f"(d.y) : "l"(v)); return d;
}
__device__ __forceinline__ void ffma2(u64& acc, u64 a, u64 b) {
    asm("fma.rn.f32x2 %0, %1, %2, %0;" : "+l"(acc) : "l"(a), "l"(b));
}
__device__ __forceinline__ void fmul2(u64& a, u64 b) {
    asm("mul.rn.f32x2 %0, %0, %1;" : "+l"(a) : "l"(b));
}
__device__ __forceinline__ void cp16(void* smem_dst, const void* gsrc) {
    unsigned s = (unsigned)__cvta_generic_to_shared(smem_dst);
    asm volatile("cp.async.cg.shared.global [%0], [%1], 16;" :: "r"(s), "l"(gsrc));
}
__device__ __forceinline__ void cp_commit() { asm volatile("cp.async.commit_group;"); }
__device__ __forceinline__ void cp_wait1()  { asm volatile("cp.async.wait_group 1;"); }
__device__ __forceinline__ void cp_wait0()  { asm volatile("cp.async.wait_group 0;"); }

// ============================================================================
// Kernel A: q = current @ Wq^T + bq      [1024,512] x [512,512] (NT)
// CTA: 64b x 64i tile, K-chunks of 64. 256 threads, 4x4 micro-tiles.
// ============================================================================
__global__ void __launch_bounds__(256) k_qproj(
    const float* __restrict__ X, const float* __restrict__ Wq,
    const float* __restrict__ bq)
{
    __shared__ __align__(16) float Xs[64][64];
    __shared__ __align__(16) float Ws[64][68];   // transposed [k][i], padded
    const int tid = threadIdx.x;
    const int bB = blockIdx.x * 64;
    const int iB = blockIdx.y * 64;
    const int i0 = (tid & 15) * 4;
    const int b0 = (tid >> 4) * 4;

    u64 acc[4][2];
#pragma unroll
    for (int a = 0; a < 4; a++) { acc[a][0] = 0ull; acc[a][1] = 0ull; }

    for (int kc = 0; kc < 8; kc++) {
#pragma unroll
        for (int it = 0; it < 4; it++) {
            int idx = tid + 256 * it;
            int r = idx >> 4, c4 = (idx & 15) * 4;
            *(float4*)&Xs[r][c4] = *(const float4*)&X[(bB + r) * 512 + kc * 64 + c4];
            float4 wv = *(const float4*)&Wq[(iB + r) * 512 + kc * 64 + c4];
            Ws[c4 + 0][r] = wv.x; Ws[c4 + 1][r] = wv.y;
            Ws[c4 + 2][r] = wv.z; Ws[c4 + 3][r] = wv.w;
        }
        __syncthreads();
#pragma unroll
        for (int k = 0; k < 64; k++) {
            ulonglong2 w2 = *(const ulonglong2*)&Ws[k][i0];
#pragma unroll
            for (int cb = 0; cb < 4; cb++) {
                float x = Xs[b0 + cb][k];
                u64 xx = pack2(x, x);
                ffma2(acc[cb][0], xx, w2.x);
                ffma2(acc[cb][1], xx, w2.y);
            }
        }
        __syncthreads();
    }
    float4 bqv = *(const float4*)&bq[iB + i0];
#pragma unroll
    for (int cb = 0; cb < 4; cb++) {
        float2 p0 = unpack2(acc[cb][0]);
        float2 p1 = unpack2(acc[cb][1]);
        float4 o = make_float4(p0.x + bqv.x, p0.y + bqv.y, p1.x + bqv.z, p1.y + bqv.w);
        *(float4*)&g_q[(bB + b0 + cb) * 512 + iB + i0] = o;
    }
}

// ============================================================================
// Kernel B: r[b,h,n] = sum_k q[b, h*64+k] * Wk[h*64+k, n]   (NN, K=64)
// CTA: (nchunk=128, btile=32, head). Full Wk chunk in smem.
// ============================================================================
__global__ void __launch_bounds__(256) k_rproj(const float* __restrict__ Wk)
{
    __shared__ __align__(16) float Wks[64][128];
    __shared__ __align__(16) float qs[32][64];
    const int tid = threadIdx.x;
    const int nc = blockIdx.x;           // 0..3  (n chunk of 128)
    const int bB = blockIdx.y * 32;      // 0..31 (b tile of 32)
    const int h  = blockIdx.z;           // 0..7

#pragma unroll
    for (int it = 0; it < 8; it++) {
        int idx = tid + 256 * it;        // 2048 float4
        int k = idx >> 5, n4 = (idx & 31) * 4;
        *(float4*)&Wks[k][n4] = *(const float4*)&Wk[(h * 64 + k) * 512 + nc * 128 + n4];
    }
#pragma unroll
    for (int it = 0; it < 2; it++) {
        int idx = tid + 256 * it;        // 512 float4
        int bb = idx >> 4, k4 = (idx & 15) * 4;
        *(float4*)&qs[bb][k4] = *(const float4*)&g_q[(bB + bb) * 512 + h * 64 + k4];
    }
    __syncthreads();

    const int n0 = (tid & 31) * 4;
    const int b0 = (tid >> 5) * 4;
    u64 acc[4][2];
#pragma unroll
    for (int a = 0; a < 4; a++) { acc[a][0] = 0ull; acc[a][1] = 0ull; }

#pragma unroll
    for (int k = 0; k < 64; k++) {
        ulonglong2 w2 = *(const ulonglong2*)&Wks[k][n0];
#pragma unroll
        for (int cb = 0; cb < 4; cb++) {
            float x = qs[b0 + cb][k];
            u64 xx = pack2(x, x);
            ffma2(acc[cb][0], xx, w2.x);
            ffma2(acc[cb][1], xx, w2.y);
        }
    }
#pragma unroll
    for (int cb = 0; cb < 4; cb++) {
        float2 p0 = unpack2(acc[cb][0]), p1 = unpack2(acc[cb][1]);
        float4 o = make_float4(p0.x, p0.y, p1.x, p1.y);
        *(float4*)&g_r[((bB + b0 + cb) * 8 + h) * 512 + nc * 128 + n0] = o;
    }
}

// ============================================================================
// Kernel C: streaming attention with online softmax.
// 1 CTA per batch row. scores[h,t] = (r[h]·x[t] + sb[h])/8 + mask[t],
// c[h,:] = softmax-weighted sum of x[t,:]. r fragment & acc live in registers,
// warp w owns j-slice [w*64, w*64+64), lane (h=l>>2, g=l&3) owns 16 j's x 1 head.
// ============================================================================
__device__ __forceinline__ void prefetch_tile(
    float* dst, const float* __restrict__ prev, const float* __restrict__ cur,
    int b, int tile, int tid)
{
#pragma unroll
    for (int i = 0; i < 2; i++) {
        int idx = tid + 256 * i;        // 512 float4 = 4 rows x 512 floats
        int tr = idx >> 7;
        int c = (idx & 127) * 4;
        int gt = tile * TTILE + tr;
        const float* src = (gt < HIST)
            ? (prev + ((long)b * HIST + gt) * 512 + c)
            : (cur + (long)b * 512 + c);
        cp16(dst + tr * 512 + c, src);
    }
}

__global__ void __launch_bounds__(256) k_attn(
    const float* __restrict__ cur, const float* __restrict__ prev,
    const float* __restrict__ mask, const float* __restrict__ bk)
{
    __shared__ __align__(16) float r_s[NH * DM];       // 16 KB
    __shared__ __align__(16) float xb[2][TTILE][DM];   // 16 KB
    __shared__ float s_part[8][8][TTILE];
    __shared__ float p_s[8][TTILE];
    __shared__ float m_s[8], l_s[8], scale_s[8], sb_s[8];
    __shared__ float mask_s[TT];

    const int tid = threadIdx.x;
    const int b = blockIdx.x;
    const int w = tid >> 5, lane = tid & 31;
    const int h = lane >> 2, g = lane & 3;

#pragma unroll
    for (int it = 0; it < 4; it++) {
        int idx = tid + 256 * it;
        *(float4*)&r_s[idx * 4] = *(const float4*)&g_r[(long)b * 4096 + idx * 4];
    }
    if (tid < TT) mask_s[tid] = mask[b * TT + tid];
    if (tid < 8) { m_s[tid] = __int_as_float(0xff800000u); l_s[tid] = 0.f; }
    {   // sb[h] = q[b,h,:]·bk[h,:]; warp w handles head w
        float q1 = g_q[b * 512 + w * 64 + lane];
        float q2 = g_q[b * 512 + w * 64 + 32 + lane];
        float s = q1 * bk[w * 64 + lane] + q2 * bk[w * 64 + 32 + lane];
#pragma unroll
        for (int o = 16; o; o >>= 1) s += __shfl_xor_sync(0xffffffffu, s, o);
        if (lane == 0) sb_s[w] = s;
    }
    __syncthreads();

    u64 rf[8];
    {
        const float* rp = &r_s[h * 512 + w * 64 + g * 16];
#pragma unroll
        for (int i = 0; i < 8; i++) rf[i] = *(const u64*)(rp + 2 * i);
    }
    u64 acc[8];
#pragma unroll
    for (int i = 0; i < 8; i++) acc[i] = 0ull;

    prefetch_tile(&xb[0][0][0], prev, cur, b, 0, tid);
    cp_commit();

    for (int tile = 0; tile < NTILES; tile++) {
        const int buf = tile & 1;
        if (tile + 1 < NTILES) {
            prefetch_tile(&xb[buf ^ 1][0][0], prev, cur, b, tile + 1, tid);
            cp_commit();
            cp_wait1();
        } else {
            cp_wait0();
        }
        __syncthreads();

        const float* xbase = &xb[buf][0][w * 64 + g * 16];
        // ---- scores (partial dots, x read 1x) ----
#pragma unroll
        for (int t = 0; t < TTILE; t++) {
            const u64* xp = (const u64*)(xbase + t * 512);
            u64 s2 = 0ull;
#pragma unroll
            for (int i = 0; i < 8; i++) ffma2(s2, rf[i], xp[i]);
            float2 sf = unpack2(s2);
            float s = sf.x + sf.y;
            s += __shfl_xor_sync(0xffffffffu, s, 1);
            s += __shfl_xor_sync(0xffffffffu, s, 2);
            if (g == 0) s_part[w][h][t] = s;
        }
        __syncthreads();

        // ---- reduce + online softmax (warp 0: lane = hh*4 + tt) ----
        if (tid < 32) {
            int hh = tid >> 2, tt = tid & 3;
            float sum = 0.f;
#pragma unroll
            for (int w2 = 0; w2 < 8; w2++) sum += s_part[w2][hh][tt];
            float logit = (sum + sb_s[hh]) * 0.125f + mask_s[tile * TTILE + tt];
            float mx = logit;
            mx = fmaxf(mx, __shfl_xor_sync(0xffffffffu, mx, 1));
            mx = fmaxf(mx, __shfl_xor_sync(0xffffffffu, mx, 2));
            float m_old = m_s[hh];
            float m_new = fmaxf(m_old, mx);
            float p = __expf(logit - m_new);
            float ps = p;
            ps += __shfl_xor_sync(0xffffffffu, ps, 1);
            ps += __shfl_xor_sync(0xffffffffu, ps, 2);
            p_s[hh][tt] = p;
            if (tt == 0) {
                float scl = __expf(m_old - m_new);
                scale_s[hh] = scl;
                l_s[hh] = l_s[hh] * scl + ps;
                m_s[hh] = m_new;
            }
        }
        __syncthreads();

        // ---- rescale + accumulate weighted x ----
        {
            float scl = scale_s[h];
            u64 sclp = pack2(scl, scl);
#pragma unroll
            for (int i = 0; i < 8; i++) fmul2(acc[i], sclp);
#pragma unroll
            for (int t = 0; t < TTILE; t++) {
                const u64* xp = (const u64*)(xbase + t * 512);
                float pv = p_s[h][t];
                u64 pvp = pack2(pv, pv);
#pragma unroll
                for (int i = 0; i < 8; i++) ffma2(acc[i], pvp, xp[i]);
            }
        }
        __syncthreads();   // protect xb[buf] before next prefetch overwrites it
    }

    float inv = 1.0f / l_s[h];
    float* cpo = &g_c[((long)b * 8 + h) * 512 + w * 64 + g * 16];
#pragma unroll
    for (int i = 0; i < 8; i++) {
        float2 v = unpack2(acc[i]);
        v.x *= inv; v.y *= inv;
        *(float2*)(cpo + 2 * i) = v;
    }
}

// ============================================================================
// Kernel D: out[b, h*64+d] = sum_j c[b,h,j] * Wv[h*64+d, j] + bv  (NT, per head)
// ============================================================================
__global__ void __launch_bounds__(256) k_oproj(
    const float* __restrict__ Wv, const float* __restrict__ bv,
    float* __restrict__ out)
{
    __shared__ __align__(16) float Cs[64][64];
    __shared__ __align__(16) float Ws[64][68];   // transposed [j][d]
    const int tid = threadIdx.x;
    const int bB = blockIdx.x * 64;
    const int h  = blockIdx.y;
    const int d0 = (tid & 15) * 4;
    const int b0 = (tid >> 4) * 4;

    u64 acc[4][2];
#pragma unroll
    for (int a = 0; a < 4; a++) { acc[a][0] = 0ull; acc[a][1] = 0ull; }

    for (int jc = 0; jc < 8; jc++) {
#pragma unroll
        for (int it = 0; it < 4; it++) {
            int idx = tid + 256 * it;
            int r = idx >> 4, c4 = (idx & 15) * 4;
            *(float4*)&Cs[r][c4] =
                *(const float4*)&g_c[((long)(bB + r) * 8 + h) * 512 + jc * 64 + c4];
            float4 wv = *(const float4*)&Wv[(h * 64 + r) * 512 + jc * 64 + c4];
            Ws[c4 + 0][r] = wv.x; Ws[c4 + 1][r] = wv.y;
            Ws[c4 + 2][r] = wv.z; Ws[c4 + 3][r] = wv.w;
        }
        __syncthreads();
#pragma unroll
        for (int j = 0; j < 64; j++) {
            ulonglong2 w2 = *(const ulonglong2*)&Ws[j][d0];
#pragma unroll
            for (int cb = 0; cb < 4; cb++) {
                float x = Cs[b0 + cb][j];
                u64 xx = pack2(x, x);
                ffma2(acc[cb][0], xx, w2.x);
                ffma2(acc[cb][1], xx, w2.y);
            }
        }
        __syncthreads();
    }
    float4 bvv = *(const float4*)&bv[h * 64 + d0];
#pragma unroll
    for (int cb = 0; cb < 4; cb++) {
        float2 p0 = unpack2(acc[cb][0]), p1 = unpack2(acc[cb][1]);
        float4 o = make_float4(p0.x + bvv.x, p0.y + bvv.y, p1.x + bvv.z, p1.y + bvv.w);
        *(float4*)&out[(bB + b0 + cb) * 512 + h * 64 + d0] = o;
    }
}

// ============================================================================
extern "C" void kernel_launch(void* const* d_in, const int* in_sizes, int n_in,
                              void* d_out, int out_size)
{
    const float* cur  = (const float*)d_in[0];   // [1024, 512]
    const float* prev = (const float*)d_in[1];   // [1024, 199, 512]
    const float* mask = (const float*)d_in[2];   // [1024, 200]
    const float* Wq   = (const float*)d_in[3];   // [512, 512]
    const float* bq   = (const float*)d_in[4];   // [512]
    const float* Wk   = (const float*)d_in[5];   // [512, 512]
    const float* bk   = (const float*)d_in[6];   // [512]
    const float* Wv   = (const float*)d_in[7];   // [512, 512]
    const float* bv   = (const float*)d_in[8];   // [512]
    float* out = (float*)d_out;                  // [1024, 512]

    k_qproj<<<dim3(16, 8), 256>>>(cur, Wq, bq);
    k_rproj<<<dim3(4, 32, 8), 256>>>(Wk);
    k_attn <<<dim3(1024), 256>>>(cur, prev, mask, bk);
    k_oproj<<<dim3(16, 8), 256>>>(Wv, bv, out);
}